// round 13
// baseline (speedup 1.0000x reference)
#include <cuda_runtime.h>

#define BATCH 16
#define CHN   8
#define HH    512
#define WW    512
#define HW    (HH * WW)
#define TW    128
#define TH    8
#define TILES_X (WW / TW)   // 4
#define TILES_Y (HH / TH)   // 64
#define NBLK (TILES_X * TILES_Y * BATCH)  // 4096

#define EPR    136                  // pair entries per row (8B each) -> 1088B pitch
#define ROWB   (EPR * 8)            // 1088
#define NROWS  (TH + 2)             // 10
#define CSTRIDE (NROWS * ROWB)      // 10880 (one channel slot)

// Scratch (device globals: allocation-free rule)
__device__ float g_y[BATCH * CHN * HH * WW];
__device__ float g_part[NBLK * 16];
__device__ float g_scale[CHN];
__device__ float g_shift[CHN];
// Zero-initialized, never written. OOB pointers redirect here and may advance
// by HW up to 7 times (uniform stride -> no per-pointer stride registers).
__device__ float g_zpad[7 * HW + 2 * WW + 64];

// ---------- helpers ----------
__device__ __forceinline__ void fma2(unsigned long long& d, unsigned long long a,
                                     unsigned long long b) {
    asm("fma.rn.f32x2 %0, %1, %2, %0;" : "+l"(d) : "l"(a), "l"(b));
}
__device__ __forceinline__ void add2(unsigned long long& d, unsigned long long a) {
    asm("add.rn.f32x2 %0, %0, %1;" : "+l"(d) : "l"(a));
}
__device__ __forceinline__ float2 up2(unsigned long long v) {
    float2 f;
    asm("mov.b64 {%0, %1}, %2;" : "=f"(f.x), "=f"(f.y) : "l"(v));
    return f;
}
__device__ __forceinline__ int swz(int e) {           // XOR swizzle on pair-entry index
    return e ^ (((e >> 4) & 7) << 1);
}
__device__ __forceinline__ void stpair(unsigned addr, float a, float b) {
    asm volatile("st.shared.v2.f32 [%0], {%1, %2};" :: "r"(addr), "f"(a), "f"(b));
}
__device__ __forceinline__ float maskf(float v, unsigned m) {   // bitwise zero (NaN-safe)
    return __uint_as_float(__float_as_uint(v) & m);
}
#define LDS128I(lo, hi, addr, IMM) \
    asm("ld.shared.v2.u64 {%0, %1}, [%2+" IMM "];" : "=l"(lo), "=l"(hi) : "r"(addr))

// taps: 8 couts x (3 taps x 4 pairs) per (cin,kh); adjacent-cout weight pairs
// fetched with one broadcast LDS.128.
__device__ __forceinline__ void taps(unsigned long long acc[8][4],
                                     const ulonglong2 L[5],
                                     const unsigned long long* __restrict__ wrow) {
    #pragma unroll
    for (int cp = 0; cp < 4; cp++) {
        ulonglong2 WA = *(const ulonglong2*)(wrow + 2 * cp);
        ulonglong2 WB = *(const ulonglong2*)(wrow + 8 + 2 * cp);
        ulonglong2 WC = *(const ulonglong2*)(wrow + 16 + 2 * cp);
        const int c0 = 2 * cp, c1 = 2 * cp + 1;
        #pragma unroll
        for (int m = 0; m < 4; m++) {
            fma2(acc[c0][m], L[m].x, WA.x);
            fma2(acc[c1][m], L[m].x, WA.y);
            fma2(acc[c0][m], L[m].y, WB.x);
            fma2(acc[c1][m], L[m].y, WB.y);
            fma2(acc[c0][m], L[m + 1].x, WC.x);
            fma2(acc[c1][m], L[m + 1].x, WC.y);
        }
    }
}

// ---------- Kernel 1: conv3x3 + bias -> g_y, per-block channel sum/sumsq ----------
// 128 threads: tx = tid&15 (8-px group), ty = tid>>4 (row). 8 couts per thread.
// 2-slot smem ring over input channels; LDG prefetch of channel c+1 in flight
// during compute of channel c. Bounds hoisted into zero-pad-redirected pointers
// with UNIFORM stride HW; halo scalar = pr[4] with bitwise mask.
__global__ __launch_bounds__(128, 4) void conv_kernel(
    const float* __restrict__ x, const float* __restrict__ lin_w,
    const float* __restrict__ lin_b) {
    __shared__ char s_tile[2 * CSTRIDE];              // 21760 B (2 channel slots)
    __shared__ float2 s_w[CHN * 9 * 8];               // (w,w) pairs: 4608 B
    __shared__ float2 s_bias[8];

    const int tid = threadIdx.x;
    const int tx = tid & 15;          // 8-px group
    const int ty = tid >> 4;          // row 0..7
    const int bw = blockIdx.x, bh = blockIdx.y, b = blockIdx.z;
    const int col0 = bw * TW, row0 = bh * TH;
    const unsigned sbase = (unsigned)__cvta_generic_to_shared(s_tile);

    // Weights: s_w[(cin*9 + tap)*8 + cout] = (w, w)
    for (int i = tid; i < CHN * 9 * 8; i += 128) {
        int cout = i & 7;
        int t = (i >> 3) % 9;
        int cin = i / 72;
        float w = lin_w[(cin * 8 + cout) * 9 + t];
        s_w[i] = make_float2(w, w);
    }
    if (tid < 8) {
        float bs = 0.f;
        #pragma unroll
        for (int cin = 0; cin < 8; cin++) bs += lin_b[cin * 8 + tid];
        s_bias[tid] = make_float2(bs, bs);
    }

    // Accumulators (bias added in epilogue)
    unsigned long long acc[8][4];
    #pragma unroll
    for (int co = 0; co < 8; co++)
        #pragma unroll
        for (int m = 0; m < 4; m++) acc[co][m] = 0ull;

    // Thread's 5 LDS.128 base offsets (row ty, slot 0)
    unsigned off0, off1, off2, off3, off4;
    {
        int e0 = 8 * tx;
        off0 = sbase + ty * ROWB + swz(e0 + 0) * 8;
        off1 = sbase + ty * ROWB + swz(e0 + 2) * 8;
        off2 = sbase + ty * ROWB + swz(e0 + 4) * 8;
        off3 = sbase + ty * ROWB + swz(e0 + 6) * 8;
        off4 = sbase + ty * ROWB + swz(e0 + 8) * 8;
    }

    // ---- one-time staging pointer setup (channel 0; advance by HW) ----
    const int r0i = tid >> 5, chk = tid & 31;   // staging row group / 4-col chunk
    const int gcc = col0 + chk * 4;
    const bool rowok2 = (tid < 64);
    const int er = tid >> 1, eside = tid & 1;

    const float* xb = x + (size_t)b * CHN * HW;   // channel 0 base

    const float *pr0, *pr1, *pr2, *pea, *peb;
    unsigned hmu;
    {
        int gr0 = row0 + r0i - 1, gr1 = row0 + r0i + 3, gr2 = row0 + r0i + 7;
        bool k0 = (unsigned)gr0 < HH, k1 = (unsigned)gr1 < HH,
             k2 = rowok2 && (unsigned)gr2 < HH;
        pr0 = k0 ? xb + (size_t)gr0 * WW + gcc : g_zpad;
        pr1 = k1 ? xb + (size_t)gr1 * WW + gcc : g_zpad;
        pr2 = k2 ? xb + (size_t)gr2 * WW + gcc : g_zpad;
        hmu = (gcc + 4 < WW) ? 0xFFFFFFFFu : 0u;   // halo column validity
        // edge (tid<20): row row0+er-1; eside 0 -> entries (x[col0-1], x[col0]),
        // eside 1 -> (x[col0+128], 0)
        int gre = row0 + er - 1;
        bool ke = (tid < 20) && ((unsigned)gre < HH);
        bool a_ok = ke && (eside ? (col0 + 128 < WW) : (col0 >= 1));
        bool b_ok = ke && !eside;
        const float* rpe = xb + (size_t)gre * WW;
        pea = a_ok ? (eside ? rpe + col0 + 128 : rpe + col0 - 1) : g_zpad;
        peb = b_ok ? rpe + col0 : g_zpad;
    }

    // prefetch registers
    float4 pA0, pA1, pA2;
    float pb0, pb1, pb2, pe0, pe1;

#define LDGCH()                                                                \
    {                                                                          \
        pA0 = *(const float4*)pr0;  pb0 = pr0[4];                              \
        pA1 = *(const float4*)pr1;  pb1 = pr1[4];                              \
        pA2 = *(const float4*)pr2;  pb2 = pr2[4];                              \
        pe0 = pea[0];  pe1 = peb[0];                                           \
        pr0 += HW; pr1 += HW; pr2 += HW; pea += HW; peb += HW;                 \
    }

#define STSCH(slotoff)                                                         \
    {                                                                          \
        const unsigned rb = sbase + (slotoff);                                 \
        const int e = chk * 4 + 1;                                             \
        {   unsigned ra = rb + r0i * ROWB;                                     \
            stpair(ra + swz(e) * 8,     pA0.x, pA0.y);                         \
            stpair(ra + swz(e + 1) * 8, pA0.y, pA0.z);                         \
            stpair(ra + swz(e + 2) * 8, pA0.z, pA0.w);                         \
            stpair(ra + swz(e + 3) * 8, pA0.w, maskf(pb0, hmu)); }             \
        {   unsigned ra = rb + (r0i + 4) * ROWB;                               \
            stpair(ra + swz(e) * 8,     pA1.x, pA1.y);                         \
            stpair(ra + swz(e + 1) * 8, pA1.y, pA1.z);                         \
            stpair(ra + swz(e + 2) * 8, pA1.z, pA1.w);                         \
            stpair(ra + swz(e + 3) * 8, pA1.w, maskf(pb1, hmu)); }             \
        if (rowok2) {                                                          \
            unsigned ra = rb + (r0i + 8) * ROWB;                               \
            stpair(ra + swz(e) * 8,     pA2.x, pA2.y);                         \
            stpair(ra + swz(e + 1) * 8, pA2.y, pA2.z);                         \
            stpair(ra + swz(e + 2) * 8, pA2.z, pA2.w);                         \
            stpair(ra + swz(e + 3) * 8, pA2.w, maskf(pb2, hmu)); }             \
        if (tid < 20) {                                                        \
            unsigned ra = rb + er * ROWB;                                      \
            int ee = eside ? 129 : 0;                                          \
            stpair(ra + swz(ee) * 8, pe0, pe1);                                \
        }                                                                      \
    }

    const unsigned long long* __restrict__ wp = (const unsigned long long*)s_w;

    LDGCH();                       // prologue prefetch (channel 0)

    #pragma unroll 1
    for (int c = 0; c < 8; c++) {
        const unsigned slotoff = (unsigned)(c & 1) * CSTRIDE;
        STSCH(slotoff);            // store channel c (prefetched last iter)
        if (c < 7) LDGCH();        // prefetch next channel (in flight during compute)
        __syncthreads();

        unsigned o0 = off0 + slotoff, o1 = off1 + slotoff, o2 = off2 + slotoff,
                 o3 = off3 + slotoff, o4 = off4 + slotoff;
        {   // kh = 0
            ulonglong2 L[5];
            LDS128I(L[0].x, L[0].y, o0, "0");
            LDS128I(L[1].x, L[1].y, o1, "0");
            LDS128I(L[2].x, L[2].y, o2, "0");
            LDS128I(L[3].x, L[3].y, o3, "0");
            LDS128I(L[4].x, L[4].y, o4, "0");
            taps(acc, L, wp);
        }
        {   // kh = 1
            ulonglong2 L[5];
            LDS128I(L[0].x, L[0].y, o0, "1088");
            LDS128I(L[1].x, L[1].y, o1, "1088");
            LDS128I(L[2].x, L[2].y, o2, "1088");
            LDS128I(L[3].x, L[3].y, o3, "1088");
            LDS128I(L[4].x, L[4].y, o4, "1088");
            taps(acc, L, wp + 24);
        }
        {   // kh = 2
            ulonglong2 L[5];
            LDS128I(L[0].x, L[0].y, o0, "2176");
            LDS128I(L[1].x, L[1].y, o1, "2176");
            LDS128I(L[2].x, L[2].y, o2, "2176");
            LDS128I(L[3].x, L[3].y, o3, "2176");
            LDS128I(L[4].x, L[4].y, o4, "2176");
            taps(acc, L, wp + 48);
        }
        wp += 72;
    }

    // ---- epilogue: add bias, store y, channel sums ----
    const int orow = row0 + ty;
    float vals[16];
    #pragma unroll
    for (int co = 0; co < 8; co++) {
        unsigned long long bz = ((const unsigned long long*)s_bias)[co];
        #pragma unroll
        for (int m = 0; m < 4; m++) add2(acc[co][m], bz);
        size_t off = ((size_t)(b * 8 + co) * HH + orow) * WW + col0 + 8 * tx;
        *(ulonglong2*)(g_y + off)     = make_ulonglong2(acc[co][0], acc[co][1]);
        *(ulonglong2*)(g_y + off + 4) = make_ulonglong2(acc[co][2], acc[co][3]);
        unsigned long long ss = 0ull, sq = 0ull;
        #pragma unroll
        for (int m = 0; m < 4; m++) {
            add2(ss, acc[co][m]);
            fma2(sq, acc[co][m], acc[co][m]);
        }
        float2 fs = up2(ss), fq = up2(sq);
        vals[co] = fs.x + fs.y;
        vals[8 + co] = fq.x + fq.y;
    }
    #pragma unroll
    for (int v = 0; v < 16; v++) {
        float t = vals[v];
        #pragma unroll
        for (int o = 16; o > 0; o >>= 1) t += __shfl_xor_sync(0xFFFFFFFFu, t, o);
        vals[v] = t;
    }
    float* sred = (float*)s_tile;   // slot 0 start; final compute read slot 1
    int wid = tid >> 5, lane = tid & 31;
    if (lane == 0) {
        #pragma unroll
        for (int v = 0; v < 16; v++) sred[wid * 16 + v] = vals[v];
    }
    __syncthreads();
    if (tid < 16) {
        float t = sred[tid] + sred[16 + tid] + sred[32 + tid] + sred[48 + tid];
        int blin = (b * gridDim.y + bh) * gridDim.x + bw;
        g_part[blin * 16 + tid] = t;
    }
#undef LDGCH
#undef STSCH
}

// ---------- Kernel 2: finalize statistics ----------
__global__ __launch_bounds__(1024) void stats_kernel(const float* __restrict__ gamma,
                                                     const float* __restrict__ beta) {
    __shared__ float red[1024];
    int tid = threadIdx.x;
    int v = tid & 15, g = tid >> 4;   // 64 groups
    float s = 0.f;
    for (int i = g; i < NBLK; i += 64) s += g_part[i * 16 + v];
    red[tid] = s;
    __syncthreads();
    float tot = 0.f;
    if (tid < 16) {
        #pragma unroll
        for (int gg = 0; gg < 64; gg++) tot += red[gg * 16 + tid];
    }
    __syncthreads();
    if (tid < 16) red[tid] = tot;
    __syncthreads();
    if (tid < 8) {
        const float n = (float)(BATCH * HH * WW);
        float mean = red[tid] / n;
        float var = red[tid + 8] / n - mean * mean;
        float sc = gamma[tid] * rsqrtf(var + 1e-5f);
        g_scale[tid] = sc;
        g_shift[tid] = beta[tid] - mean * sc;
    }
}

// ---------- Kernel 3: normalize + ReLU ----------
__global__ __launch_bounds__(256) void norm_kernel(float* __restrict__ out) {
    __shared__ float ssc[8], ssh[8];
    if (threadIdx.x < 8) {
        ssc[threadIdx.x] = g_scale[threadIdx.x];
        ssh[threadIdx.x] = g_shift[threadIdx.x];
    }
    __syncthreads();
    int i = blockIdx.x * 256 + threadIdx.x;
    int c = (i >> 16) & 7;
    float4 v = ((const float4*)g_y)[i];
    float s = ssc[c], h = ssh[c];
    v.x = fmaxf(fmaf(v.x, s, h), 0.f);
    v.y = fmaxf(fmaf(v.y, s, h), 0.f);
    v.z = fmaxf(fmaf(v.z, s, h), 0.f);
    v.w = fmaxf(fmaf(v.w, s, h), 0.f);
    ((float4*)out)[i] = v;
}

extern "C" void kernel_launch(void* const* d_in, const int* in_sizes, int n_in,
                              void* d_out, int out_size) {
    const float* x     = (const float*)d_in[0];
    const float* lin_w = (const float*)d_in[1];
    const float* lin_b = (const float*)d_in[2];
    const float* gamma = (const float*)d_in[3];
    const float* beta  = (const float*)d_in[4];
    float* out = (float*)d_out;

    dim3 grid(TILES_X, TILES_Y, BATCH);
    conv_kernel<<<grid, 128>>>(x, lin_w, lin_b);
    stats_kernel<<<1, 1024>>>(gamma, beta);
    int n4 = BATCH * CHN * HH * WW / 4;
    norm_kernel<<<n4 / 256, 256>>>(out);
}

// round 15
// speedup vs baseline: 1.0398x; 1.0398x over previous
#include <cuda_runtime.h>

#define BATCH 16
#define CHN   8
#define HH    512
#define WW    512
#define HW    (HH * WW)              // 262144 = 2^18
#define TW    128
#define TH    8
#define TILES_X (WW / TW)   // 4
#define TILES_Y (HH / TH)   // 64
#define NBLK (TILES_X * TILES_Y * BATCH)  // 4096

#define EPR    136                  // dup entries per row (8B each) -> 1088B pitch
#define ROWB   (EPR * 8)            // 1088
#define NROWS  (TH + 2)             // 10
#define CSTRIDE (NROWS * ROWB)      // 10880 (one channel slot)

// Scratch (device globals: allocation-free rule)
__device__ float g_y[BATCH * CHN * HH * WW];     // NHWC: [b,h,w,co]
__device__ float g_part[NBLK * 16];
__device__ float g_scale[CHN];
__device__ float g_shift[CHN];
// Zero-initialized, never written. OOB pointers redirect here and advance by HW
// up to 7 times (uniform stride -> no per-pointer stride registers).
__device__ float g_zpad[7 * HW + 2 * WW + 64];

// ---------- helpers ----------
__device__ __forceinline__ void fma2(unsigned long long& d, unsigned long long a,
                                     unsigned long long b) {
    asm("fma.rn.f32x2 %0, %1, %2, %0;" : "+l"(d) : "l"(a), "l"(b));
}
__device__ __forceinline__ void add2(unsigned long long& d, unsigned long long a) {
    asm("add.rn.f32x2 %0, %0, %1;" : "+l"(d) : "l"(a));
}
__device__ __forceinline__ float2 up2(unsigned long long v) {
    float2 f;
    asm("mov.b64 {%0, %1}, %2;" : "=f"(f.x), "=f"(f.y) : "l"(v));
    return f;
}
__device__ __forceinline__ int swz(int e) {           // XOR swizzle on entry index
    return e ^ (((e >> 4) & 7) << 1);
}
__device__ __forceinline__ void stpair(unsigned addr, float a, float b) {
    asm volatile("st.shared.v2.f32 [%0], {%1, %2};" :: "r"(addr), "f"(a), "f"(b));
}
#define LDS128I(lo, hi, addr, IMM) \
    asm("ld.shared.v2.u64 {%0, %1}, [%2+" IMM "];" : "=l"(lo), "=l"(hi) : "r"(addr))

// taps: acc[cp][px] = f32x2 over couts (2cp, 2cp+1). X = dup data pair,
// W pairs natural from smem (2 LDS.128 per kw -> 4 cout-pairs).
__device__ __forceinline__ void taps(unsigned long long acc[4][8],
                                     const ulonglong2 L[5],
                                     const float* __restrict__ wk) {
    #pragma unroll
    for (int kw = 0; kw < 3; kw++) {
        ulonglong2 Wa = *(const ulonglong2*)(wk + kw * 8);       // (w0,w1),(w2,w3)
        ulonglong2 Wb = *(const ulonglong2*)(wk + kw * 8 + 4);   // (w4,w5),(w6,w7)
        #pragma unroll
        for (int px = 0; px < 8; px++) {
            const int q = px + kw;
            unsigned long long X = (q & 1) ? L[q >> 1].y : L[q >> 1].x;
            fma2(acc[0][px], X, Wa.x);
            fma2(acc[1][px], X, Wa.y);
            fma2(acc[2][px], X, Wb.x);
            fma2(acc[3][px], X, Wb.y);
        }
    }
}

// ---------- Kernel 1: conv3x3 + bias -> g_y (NHWC), per-block channel sums ----------
// 128 threads: tx = tid&15 (8-px group), ty = tid>>4 (row). cout-pairs in f32x2.
// 2-slot smem ring over input channels; LDG prefetch of channel c+1 in flight
// during compute of channel c. Tile entries are DUPLICATED (x,x) pairs.
__global__ __launch_bounds__(128, 4) void conv_kernel(
    const float* __restrict__ x, const float* __restrict__ lin_w,
    const float* __restrict__ lin_b) {
    __shared__ char s_tile[2 * CSTRIDE];              // 21760 B (2 channel slots)
    __shared__ float s_w[CHN * 9 * 8];                // natural f32: 2304 B
    __shared__ float s_bias[8];

    const int tid = threadIdx.x;
    const int tx = tid & 15;          // 8-px group
    const int ty = tid >> 4;          // row 0..7
    const int bw = blockIdx.x, bh = blockIdx.y, b = blockIdx.z;
    const int col0 = bw * TW, row0 = bh * TH;
    const unsigned sbase = (unsigned)__cvta_generic_to_shared(s_tile);

    // Weights: s_w[(cin*9 + tap)*8 + cout] = w (natural, cout-contiguous)
    for (int i = tid; i < CHN * 9 * 8; i += 128) {
        int cout = i & 7;
        int t = (i >> 3) % 9;
        int cin = i / 72;
        s_w[i] = lin_w[(cin * 8 + cout) * 9 + t];
    }
    if (tid < 8) {
        float bs = 0.f;
        #pragma unroll
        for (int cin = 0; cin < 8; cin++) bs += lin_b[cin * 8 + tid];
        s_bias[tid] = bs;
    }

    // Accumulators: acc[cp][px], pair = couts (2cp, 2cp+1). Bias in epilogue.
    unsigned long long acc[4][8];
    #pragma unroll
    for (int cp = 0; cp < 4; cp++)
        #pragma unroll
        for (int px = 0; px < 8; px++) acc[cp][px] = 0ull;

    // Thread's 5 LDS.128 base offsets (row ty, slot 0); entries e0..e0+9
    unsigned off0, off1, off2, off3, off4;
    {
        int e0 = 8 * tx;
        off0 = sbase + ty * ROWB + swz(e0 + 0) * 8;
        off1 = sbase + ty * ROWB + swz(e0 + 2) * 8;
        off2 = sbase + ty * ROWB + swz(e0 + 4) * 8;
        off3 = sbase + ty * ROWB + swz(e0 + 6) * 8;
        off4 = sbase + ty * ROWB + swz(e0 + 8) * 8;
    }

    // ---- one-time staging pointer setup (channel 0; advance by HW) ----
    const int r0i = tid >> 5, chk = tid & 31;   // staging row group / 4-col chunk
    const int gcc = col0 + chk * 4;
    const bool rowok2 = (tid < 64);
    const int er = tid >> 1, eside = tid & 1;

    const float* xb = x + (size_t)b * CHN * HW;   // channel 0 base

    const float *pr0, *pr1, *pr2, *pea;
    {
        int gr0 = row0 + r0i - 1, gr1 = row0 + r0i + 3, gr2 = row0 + r0i + 7;
        bool k0 = (unsigned)gr0 < HH, k1 = (unsigned)gr1 < HH,
             k2 = rowok2 && (unsigned)gr2 < HH;
        pr0 = k0 ? xb + (size_t)gr0 * WW + gcc : g_zpad;
        pr1 = k1 ? xb + (size_t)gr1 * WW + gcc : g_zpad;
        pr2 = k2 ? xb + (size_t)gr2 * WW + gcc : g_zpad;
        // edge (tid<20): row row0+er-1; eside 0 -> entry 0 = x[col0-1],
        // eside 1 -> entry 129 = x[col0+128]
        int gre = row0 + er - 1;
        bool ke = (tid < 20) && ((unsigned)gre < HH);
        bool a_ok = ke && (eside ? (col0 + 128 < WW) : (col0 >= 1));
        pea = a_ok ? xb + (size_t)gre * WW + (eside ? col0 + 128 : col0 - 1)
                   : g_zpad;
    }

    // prefetch registers
    float4 pA0, pA1, pA2;
    float pe0;

#define LDGCH()                                                                \
    {                                                                          \
        pA0 = *(const float4*)pr0;                                             \
        pA1 = *(const float4*)pr1;                                             \
        pA2 = *(const float4*)pr2;                                             \
        pe0 = pea[0];                                                          \
        pr0 += HW; pr1 += HW; pr2 += HW; pea += HW;                            \
    }

#define STSCH(slotoff)                                                         \
    {                                                                          \
        const unsigned rb = sbase + (slotoff);                                 \
        const int e = chk * 4 + 1;                                             \
        {   unsigned ra = rb + r0i * ROWB;                                     \
            stpair(ra + swz(e) * 8,     pA0.x, pA0.x);                         \
            stpair(ra + swz(e + 1) * 8, pA0.y, pA0.y);                         \
            stpair(ra + swz(e + 2) * 8, pA0.z, pA0.z);                         \
            stpair(ra + swz(e + 3) * 8, pA0.w, pA0.w); }                       \
        {   unsigned ra = rb + (r0i + 4) * ROWB;                               \
            stpair(ra + swz(e) * 8,     pA1.x, pA1.x);                         \
            stpair(ra + swz(e + 1) * 8, pA1.y, pA1.y);                         \
            stpair(ra + swz(e + 2) * 8, pA1.z, pA1.z);                         \
            stpair(ra + swz(e + 3) * 8, pA1.w, pA1.w); }                       \
        if (rowok2) {                                                          \
            unsigned ra = rb + (r0i + 8) * ROWB;                               \
            stpair(ra + swz(e) * 8,     pA2.x, pA2.x);                         \
            stpair(ra + swz(e + 1) * 8, pA2.y, pA2.y);                         \
            stpair(ra + swz(e + 2) * 8, pA2.z, pA2.z);                         \
            stpair(ra + swz(e + 3) * 8, pA2.w, pA2.w); }                       \
        if (tid < 20) {                                                        \
            unsigned ra = rb + er * ROWB;                                      \
            int ee = eside ? 129 : 0;                                          \
            stpair(ra + swz(ee) * 8, pe0, pe0);                                \
        }                                                                      \
    }

    const float* __restrict__ wk = s_w;

    LDGCH();                       // prologue prefetch (channel 0)

    #pragma unroll 1
    for (int c = 0; c < 8; c++) {
        const unsigned slotoff = (unsigned)(c & 1) * CSTRIDE;
        STSCH(slotoff);            // store channel c (prefetched last iter)
        if (c < 7) LDGCH();        // prefetch next channel (in flight during compute)
        __syncthreads();

        unsigned o0 = off0 + slotoff, o1 = off1 + slotoff, o2 = off2 + slotoff,
                 o3 = off3 + slotoff, o4 = off4 + slotoff;
        {   // kh = 0
            ulonglong2 L[5];
            LDS128I(L[0].x, L[0].y, o0, "0");
            LDS128I(L[1].x, L[1].y, o1, "0");
            LDS128I(L[2].x, L[2].y, o2, "0");
            LDS128I(L[3].x, L[3].y, o3, "0");
            LDS128I(L[4].x, L[4].y, o4, "0");
            taps(acc, L, wk);
        }
        {   // kh = 1
            ulonglong2 L[5];
            LDS128I(L[0].x, L[0].y, o0, "1088");
            LDS128I(L[1].x, L[1].y, o1, "1088");
            LDS128I(L[2].x, L[2].y, o2, "1088");
            LDS128I(L[3].x, L[3].y, o3, "1088");
            LDS128I(L[4].x, L[4].y, o4, "1088");
            taps(acc, L, wk + 24);
        }
        {   // kh = 2
            ulonglong2 L[5];
            LDS128I(L[0].x, L[0].y, o0, "2176");
            LDS128I(L[1].x, L[1].y, o1, "2176");
            LDS128I(L[2].x, L[2].y, o2, "2176");
            LDS128I(L[3].x, L[3].y, o3, "2176");
            LDS128I(L[4].x, L[4].y, o4, "2176");
            taps(acc, L, wk + 48);
        }
        wk += 72;
    }

    // ---- epilogue: add bias, store y (NHWC), channel sums ----
    const int orow = row0 + ty;
    float vals[16];
    const unsigned long long* bp = (const unsigned long long*)s_bias;
    #pragma unroll
    for (int cp = 0; cp < 4; cp++) {
        unsigned long long bz = bp[cp];
        #pragma unroll
        for (int px = 0; px < 8; px++) add2(acc[cp][px], bz);
        unsigned long long ss = 0ull, sq = 0ull;
        #pragma unroll
        for (int px = 0; px < 8; px++) {
            add2(ss, acc[cp][px]);
            fma2(sq, acc[cp][px], acc[cp][px]);
        }
        float2 fs = up2(ss), fq = up2(sq);
        vals[2 * cp] = fs.x;      vals[2 * cp + 1] = fs.y;
        vals[8 + 2 * cp] = fq.x;  vals[9 + 2 * cp] = fq.y;
    }
    {
        const size_t pbase = ((size_t)b * HH + orow) * WW + col0 + 8 * tx;
        #pragma unroll
        for (int px = 0; px < 8; px++) {
            float* gp = g_y + (pbase + px) * 8;
            *(ulonglong2*)gp       = make_ulonglong2(acc[0][px], acc[1][px]);
            *(ulonglong2*)(gp + 4) = make_ulonglong2(acc[2][px], acc[3][px]);
        }
    }
    #pragma unroll
    for (int v = 0; v < 16; v++) {
        float t = vals[v];
        #pragma unroll
        for (int o = 16; o > 0; o >>= 1) t += __shfl_xor_sync(0xFFFFFFFFu, t, o);
        vals[v] = t;
    }
    float* sred = (float*)s_tile;
    int wid = tid >> 5, lane = tid & 31;
    if (lane == 0) {
        #pragma unroll
        for (int v = 0; v < 16; v++) sred[wid * 16 + v] = vals[v];
    }
    __syncthreads();
    if (tid < 16) {
        float t = sred[tid] + sred[16 + tid] + sred[32 + tid] + sred[48 + tid];
        int blin = (b * gridDim.y + bh) * gridDim.x + bw;
        g_part[blin * 16 + tid] = t;
    }
#undef LDGCH
#undef STSCH
}

// ---------- Kernel 2: finalize statistics ----------
__global__ __launch_bounds__(1024) void stats_kernel(const float* __restrict__ gamma,
                                                     const float* __restrict__ beta) {
    __shared__ float red[1024];
    int tid = threadIdx.x;
    int v = tid & 15, g = tid >> 4;   // 64 groups
    float s = 0.f;
    for (int i = g; i < NBLK; i += 64) s += g_part[i * 16 + v];
    red[tid] = s;
    __syncthreads();
    float tot = 0.f;
    if (tid < 16) {
        #pragma unroll
        for (int gg = 0; gg < 64; gg++) tot += red[gg * 16 + tid];
    }
    __syncthreads();
    if (tid < 16) red[tid] = tot;
    __syncthreads();
    if (tid < 8) {
        const float n = (float)(BATCH * HH * WW);
        float mean = red[tid] / n;
        float var = red[tid + 8] / n - mean * mean;
        float sc = gamma[tid] * rsqrtf(var + 1e-5f);
        g_scale[tid] = sc;
        g_shift[tid] = beta[tid] - mean * sc;
    }
}

// ---------- Kernel 3: normalize + ReLU; NHWC y -> NCHW out ----------
// thread = one pixel: 2 coalesced LDG.128 (8 channels), 8 warp-coalesced STG.32.
__global__ __launch_bounds__(256) void norm_kernel(float* __restrict__ out) {
    __shared__ float ssc[8], ssh[8];
    if (threadIdx.x < 8) {
        ssc[threadIdx.x] = g_scale[threadIdx.x];
        ssh[threadIdx.x] = g_shift[threadIdx.x];
    }
    __syncthreads();
    size_t p = (size_t)blockIdx.x * 256 + threadIdx.x;   // pixel index
    const float* gp = g_y + p * 8;
    float4 a = *(const float4*)gp;
    float4 c = *(const float4*)(gp + 4);
    size_t bb = p >> 18;                                 // HW = 2^18
    float* ob = out + p + bb * (size_t)(7 * HW);         // = bb*8HW + hw
    ob[0 * HW] = fmaxf(fmaf(a.x, ssc[0], ssh[0]), 0.f);
    ob[1 * HW] = fmaxf(fmaf(a.y, ssc[1], ssh[1]), 0.f);
    ob[2 * HW] = fmaxf(fmaf(a.z, ssc[2], ssh[2]), 0.f);
    ob[3 * HW] = fmaxf(fmaf(a.w, ssc[3], ssh[3]), 0.f);
    ob[4 * HW] = fmaxf(fmaf(c.x, ssc[4], ssh[4]), 0.f);
    ob[5 * HW] = fmaxf(fmaf(c.y, ssc[5], ssh[5]), 0.f);
    ob[6 * HW] = fmaxf(fmaf(c.z, ssc[6], ssh[6]), 0.f);
    ob[7 * HW] = fmaxf(fmaf(c.w, ssc[7], ssh[7]), 0.f);
}

extern "C" void kernel_launch(void* const* d_in, const int* in_sizes, int n_in,
                              void* d_out, int out_size) {
    const float* x     = (const float*)d_in[0];
    const float* lin_w = (const float*)d_in[1];
    const float* lin_b = (const float*)d_in[2];
    const float* gamma = (const float*)d_in[3];
    const float* beta  = (const float*)d_in[4];
    float* out = (float*)d_out;

    dim3 grid(TILES_X, TILES_Y, BATCH);
    conv_kernel<<<grid, 128>>>(x, lin_w, lin_b);
    stats_kernel<<<1, 1024>>>(gamma, beta);
    int npix = BATCH * HH * WW;   // 4194304
    norm_kernel<<<npix / 256, 256>>>(out);
}

// round 17
// speedup vs baseline: 1.0743x; 1.0332x over previous
#include <cuda_runtime.h>

#define BATCH 16
#define CHN   8
#define HH    512
#define WW    512
#define HW    (HH * WW)              // 262144 = 2^18
#define TW    128
#define TH    8
#define TILES_X (WW / TW)   // 4
#define TILES_Y (HH / TH)   // 64
#define NBLK (TILES_X * TILES_Y * BATCH)  // 4096

#define ROWB   1088                 // bytes per row; == 64 (mod 128) -> row bank shift
#define NROWS  (TH + 2)             // 10
#define CSTRIDE (NROWS * ROWB)      // 10880 (one channel slot)

// Scratch (device globals: allocation-free rule)
__device__ float g_y[BATCH * CHN * HH * WW];     // NHWC: [b,h,w,co]
__device__ float g_part[NBLK * 16];
__device__ float g_scale[CHN];
__device__ float g_shift[CHN];
// Zero-initialized, never written. OOB pointers redirect here and advance by HW
// up to 7 times (uniform stride -> no per-pointer stride registers).
__device__ float g_zpad[7 * HW + 2 * WW + 64];

// ---------- helpers ----------
__device__ __forceinline__ void fma2(unsigned long long& d, unsigned long long a,
                                     unsigned long long b) {
    asm("fma.rn.f32x2 %0, %1, %2, %0;" : "+l"(d) : "l"(a), "l"(b));
}
__device__ __forceinline__ void add2(unsigned long long& d, unsigned long long a) {
    asm("add.rn.f32x2 %0, %0, %1;" : "+l"(d) : "l"(a));
}
__device__ __forceinline__ float2 up2(unsigned long long v) {
    float2 f;
    asm("mov.b64 {%0, %1}, %2;" : "=f"(f.x), "=f"(f.y) : "l"(v));
    return f;
}
// 16B-block permutation: conflict-free for stride-64B reads AND block writes.
__device__ __forceinline__ int perm(int Bk) {
    return Bk ^ ((Bk >> 3) & 7);
}
// entry e (8B dup pair) -> byte offset within row
__device__ __forceinline__ int eoff(int e) {
    return 16 * perm(e >> 1) + 8 * (e & 1);
}
__device__ __forceinline__ void stpair(unsigned addr, float a, float b) {
    asm volatile("st.shared.v2.f32 [%0], {%1, %2};" :: "r"(addr), "f"(a), "f"(b));
}
__device__ __forceinline__ void st128(unsigned addr, float a, float b, float c, float d) {
    asm volatile("st.shared.v4.f32 [%0], {%1, %2, %3, %4};"
                 :: "r"(addr), "f"(a), "f"(b), "f"(c), "f"(d));
}
#define LDS128I(lo, hi, addr, IMM) \
    asm("ld.shared.v2.u64 {%0, %1}, [%2+" IMM "];" : "=l"(lo), "=l"(hi) : "r"(addr))

// taps: acc[cp][px] = f32x2 over couts (2cp, 2cp+1). X = dup data pair,
// W pairs natural from smem (2 broadcast LDS.128 per kw -> 4 cout-pairs).
__device__ __forceinline__ void taps(unsigned long long acc[4][8],
                                     const ulonglong2 L[5],
                                     const float* __restrict__ wk) {
    #pragma unroll
    for (int kw = 0; kw < 3; kw++) {
        ulonglong2 Wa = *(const ulonglong2*)(wk + kw * 8);       // (w0,w1),(w2,w3)
        ulonglong2 Wb = *(const ulonglong2*)(wk + kw * 8 + 4);   // (w4,w5),(w6,w7)
        #pragma unroll
        for (int px = 0; px < 8; px++) {
            const int q = px + kw;
            unsigned long long X = (q & 1) ? L[q >> 1].y : L[q >> 1].x;
            fma2(acc[0][px], X, Wa.x);
            fma2(acc[1][px], X, Wa.y);
            fma2(acc[2][px], X, Wb.x);
            fma2(acc[3][px], X, Wb.y);
        }
    }
}

// ---------- Kernel 1: conv3x3 + bias -> g_y (NHWC), per-block channel sums ----------
// 128 threads: tx = tid&15 (8-px group), ty = tid>>4 (row). cout-pairs in f32x2.
// 2-slot smem ring over input channels; LDG prefetch of channel c+1 in flight
// during compute of channel c. Tile entries = DUP (x,x) pairs, block-permuted
// so reads and writes are bank-conflict-free at the crossbar floor.
__global__ __launch_bounds__(128, 3) void conv_kernel(
    const float* __restrict__ x, const float* __restrict__ lin_w,
    const float* __restrict__ lin_b) {
    __shared__ char s_tile[2 * CSTRIDE];              // 21760 B (2 channel slots)
    __shared__ float s_w[CHN * 9 * 8];                // natural f32: 2304 B
    __shared__ float s_bias[8];

    const int tid = threadIdx.x;
    const int tx = tid & 15;          // 8-px group
    const int ty = tid >> 4;          // row 0..7
    const int bw = blockIdx.x, bh = blockIdx.y, b = blockIdx.z;
    const int col0 = bw * TW, row0 = bh * TH;
    const unsigned sbase = (unsigned)__cvta_generic_to_shared(s_tile);

    // Weights: s_w[(cin*9 + tap)*8 + cout] = w (natural, cout-contiguous)
    for (int i = tid; i < CHN * 9 * 8; i += 128) {
        int cout = i & 7;
        int t = (i >> 3) % 9;
        int cin = i / 72;
        s_w[i] = lin_w[(cin * 8 + cout) * 9 + t];
    }
    if (tid < 8) {
        float bs = 0.f;
        #pragma unroll
        for (int cin = 0; cin < 8; cin++) bs += lin_b[cin * 8 + tid];
        s_bias[tid] = bs;
    }

    // Accumulators: acc[cp][px], pair = couts (2cp, 2cp+1). Bias in epilogue.
    unsigned long long acc[4][8];
    #pragma unroll
    for (int cp = 0; cp < 4; cp++)
        #pragma unroll
        for (int px = 0; px < 8; px++) acc[cp][px] = 0ull;

    // Thread's 5 LDS.128 base offsets: block 4tx+m, row ty, slot 0.
    unsigned off0, off1, off2, off3, off4;
    {
        unsigned rbase = sbase + ty * ROWB;
        off0 = rbase + 16 * perm(4 * tx + 0);
        off1 = rbase + 16 * perm(4 * tx + 1);
        off2 = rbase + 16 * perm(4 * tx + 2);
        off3 = rbase + 16 * perm(4 * tx + 3);
        off4 = rbase + 16 * perm(4 * tx + 4);
    }

    // ---- one-time staging pointer setup (channel 0; advance by HW) ----
    const int r0i = tid >> 5, chk = tid & 31;   // staging row group / 4-col chunk
    const int gcc = col0 + chk * 4;
    const bool rowok2 = (tid < 64);
    const int er = tid >> 1, eside = tid & 1;

    const float* xb = x + (size_t)b * CHN * HW;   // channel 0 base

    const float *pr0, *pr1, *pr2, *pea;
    {
        int gr0 = row0 + r0i - 1, gr1 = row0 + r0i + 3, gr2 = row0 + r0i + 7;
        bool k0 = (unsigned)gr0 < HH, k1 = (unsigned)gr1 < HH,
             k2 = rowok2 && (unsigned)gr2 < HH;
        pr0 = k0 ? xb + (size_t)gr0 * WW + gcc : g_zpad;
        pr1 = k1 ? xb + (size_t)gr1 * WW + gcc : g_zpad;
        pr2 = k2 ? xb + (size_t)gr2 * WW + gcc : g_zpad;
        // edge (tid<20): row row0+er-1; eside 0 -> entry 0 = x[col0-1],
        // eside 1 -> entry 129 = x[col0+128]
        int gre = row0 + er - 1;
        bool ke = (tid < 20) && ((unsigned)gre < HH);
        bool a_ok = ke && (eside ? (col0 + 128 < WW) : (col0 >= 1));
        pea = a_ok ? xb + (size_t)gre * WW + (eside ? col0 + 128 : col0 - 1)
                   : g_zpad;
    }

    // Per-thread staging byte offsets within a row (chunk k covers entries
    // 4k+1..4k+4 = block 2k sub8, block 2k+1 full, block 2k+2 sub0).
    const unsigned w64a = eoff(4 * chk + 1);           // = 16*perm(2k)+8
    const unsigned w128 = 16 * perm(2 * chk + 1);
    const unsigned w64b = eoff(4 * chk + 4);           // = 16*perm(2k+2)
    const unsigned wedge = eside ? (unsigned)eoff(129) : (unsigned)eoff(0);

    // prefetch registers
    float4 pA0, pA1, pA2;
    float pe0;

#define LDGCH()                                                                \
    {                                                                          \
        pA0 = *(const float4*)pr0;                                             \
        pA1 = *(const float4*)pr1;                                             \
        pA2 = *(const float4*)pr2;                                             \
        pe0 = pea[0];                                                          \
        pr0 += HW; pr1 += HW; pr2 += HW; pea += HW;                            \
    }

#define STSCH(slotoff)                                                         \
    {                                                                          \
        const unsigned rb = sbase + (slotoff) + r0i * ROWB;                    \
        stpair(rb + w64a, pA0.x, pA0.x);                                       \
        st128 (rb + w128, pA0.y, pA0.y, pA0.z, pA0.z);                         \
        stpair(rb + w64b, pA0.w, pA0.w);                                       \
        stpair(rb + 4 * ROWB + w64a, pA1.x, pA1.x);                            \
        st128 (rb + 4 * ROWB + w128, pA1.y, pA1.y, pA1.z, pA1.z);              \
        stpair(rb + 4 * ROWB + w64b, pA1.w, pA1.w);                            \
        if (rowok2) {                                                          \
            stpair(rb + 8 * ROWB + w64a, pA2.x, pA2.x);                        \
            st128 (rb + 8 * ROWB + w128, pA2.y, pA2.y, pA2.z, pA2.z);          \
            stpair(rb + 8 * ROWB + w64b, pA2.w, pA2.w);                        \
        }                                                                      \
        if (tid < 20) {                                                        \
            unsigned ra = sbase + (slotoff) + er * ROWB + wedge;               \
            stpair(ra, pe0, pe0);                                              \
        }                                                                      \
    }

    const float* __restrict__ wk = s_w;

    LDGCH();                       // prologue prefetch (channel 0)

    #pragma unroll 1
    for (int c = 0; c < 8; c++) {
        const unsigned slotoff = (unsigned)(c & 1) * CSTRIDE;
        STSCH(slotoff);            // store channel c (prefetched last iter)
        if (c < 7) LDGCH();        // prefetch next channel (in flight during compute)
        __syncthreads();

        unsigned o0 = off0 + slotoff, o1 = off1 + slotoff, o2 = off2 + slotoff,
                 o3 = off3 + slotoff, o4 = off4 + slotoff;
        {   // kh = 0
            ulonglong2 L[5];
            LDS128I(L[0].x, L[0].y, o0, "0");
            LDS128I(L[1].x, L[1].y, o1, "0");
            LDS128I(L[2].x, L[2].y, o2, "0");
            LDS128I(L[3].x, L[3].y, o3, "0");
            LDS128I(L[4].x, L[4].y, o4, "0");
            taps(acc, L, wk);
        }
        {   // kh = 1
            ulonglong2 L[5];
            LDS128I(L[0].x, L[0].y, o0, "1088");
            LDS128I(L[1].x, L[1].y, o1, "1088");
            LDS128I(L[2].x, L[2].y, o2, "1088");
            LDS128I(L[3].x, L[3].y, o3, "1088");
            LDS128I(L[4].x, L[4].y, o4, "1088");
            taps(acc, L, wk + 24);
        }
        {   // kh = 2
            ulonglong2 L[5];
            LDS128I(L[0].x, L[0].y, o0, "2176");
            LDS128I(L[1].x, L[1].y, o1, "2176");
            LDS128I(L[2].x, L[2].y, o2, "2176");
            LDS128I(L[3].x, L[3].y, o3, "2176");
            LDS128I(L[4].x, L[4].y, o4, "2176");
            taps(acc, L, wk + 48);
        }
        wk += 72;
    }

    // ---- epilogue: add bias, store y (NHWC), channel sums ----
    const int orow = row0 + ty;
    float vals[16];
    const unsigned long long* bp = (const unsigned long long*)s_bias;
    #pragma unroll
    for (int cp = 0; cp < 4; cp++) {
        unsigned long long bz = bp[cp];
        #pragma unroll
        for (int px = 0; px < 8; px++) add2(acc[cp][px], bz);
        unsigned long long ss = 0ull, sq = 0ull;
        #pragma unroll
        for (int px = 0; px < 8; px++) {
            add2(ss, acc[cp][px]);
            fma2(sq, acc[cp][px], acc[cp][px]);
        }
        float2 fs = up2(ss), fq = up2(sq);
        vals[2 * cp] = fs.x;      vals[2 * cp + 1] = fs.y;
        vals[8 + 2 * cp] = fq.x;  vals[9 + 2 * cp] = fq.y;
    }
    {
        const size_t pbase = ((size_t)b * HH + orow) * WW + col0 + 8 * tx;
        #pragma unroll
        for (int px = 0; px < 8; px++) {
            float* gp = g_y + (pbase + px) * 8;
            *(ulonglong2*)gp       = make_ulonglong2(acc[0][px], acc[1][px]);
            *(ulonglong2*)(gp + 4) = make_ulonglong2(acc[2][px], acc[3][px]);
        }
    }
    #pragma unroll
    for (int v = 0; v < 16; v++) {
        float t = vals[v];
        #pragma unroll
        for (int o = 16; o > 0; o >>= 1) t += __shfl_xor_sync(0xFFFFFFFFu, t, o);
        vals[v] = t;
    }
    float* sred = (float*)s_tile;   // slot 0; final compute read slot 1
    int wid = tid >> 5, lane = tid & 31;
    if (lane == 0) {
        #pragma unroll
        for (int v = 0; v < 16; v++) sred[wid * 16 + v] = vals[v];
    }
    __syncthreads();
    if (tid < 16) {
        float t = sred[tid] + sred[16 + tid] + sred[32 + tid] + sred[48 + tid];
        int blin = (b * gridDim.y + bh) * gridDim.x + bw;
        g_part[blin * 16 + tid] = t;
    }
#undef LDGCH
#undef STSCH
}

// ---------- Kernel 2: finalize statistics ----------
__global__ __launch_bounds__(1024) void stats_kernel(const float* __restrict__ gamma,
                                                     const float* __restrict__ beta) {
    __shared__ float red[1024];
    int tid = threadIdx.x;
    int v = tid & 15, g = tid >> 4;   // 64 groups
    float s = 0.f;
    for (int i = g; i < NBLK; i += 64) s += g_part[i * 16 + v];
    red[tid] = s;
    __syncthreads();
    float tot = 0.f;
    if (tid < 16) {
        #pragma unroll
        for (int gg = 0; gg < 64; gg++) tot += red[gg * 16 + tid];
    }
    __syncthreads();
    if (tid < 16) red[tid] = tot;
    __syncthreads();
    if (tid < 8) {
        const float n = (float)(BATCH * HH * WW);
        float mean = red[tid] / n;
        float var = red[tid + 8] / n - mean * mean;
        float sc = gamma[tid] * rsqrtf(var + 1e-5f);
        g_scale[tid] = sc;
        g_shift[tid] = beta[tid] - mean * sc;
    }
}

// ---------- Kernel 3: normalize + ReLU; NHWC y -> NCHW out ----------
__global__ __launch_bounds__(256) void norm_kernel(float* __restrict__ out) {
    __shared__ float ssc[8], ssh[8];
    if (threadIdx.x < 8) {
        ssc[threadIdx.x] = g_scale[threadIdx.x];
        ssh[threadIdx.x] = g_shift[threadIdx.x];
    }
    __syncthreads();
    size_t p = (size_t)blockIdx.x * 256 + threadIdx.x;   // pixel index
    const float* gp = g_y + p * 8;
    float4 a = *(const float4*)gp;
    float4 c = *(const float4*)(gp + 4);
    size_t bb = p >> 18;                                 // HW = 2^18
    float* ob = out + p + bb * (size_t)(7 * HW);         // = bb*8HW + hw
    ob[0 * HW] = fmaxf(fmaf(a.x, ssc[0], ssh[0]), 0.f);
    ob[1 * HW] = fmaxf(fmaf(a.y, ssc[1], ssh[1]), 0.f);
    ob[2 * HW] = fmaxf(fmaf(a.z, ssc[2], ssh[2]), 0.f);
    ob[3 * HW] = fmaxf(fmaf(a.w, ssc[3], ssh[3]), 0.f);
    ob[4 * HW] = fmaxf(fmaf(c.x, ssc[4], ssh[4]), 0.f);
    ob[5 * HW] = fmaxf(fmaf(c.y, ssc[5], ssh[5]), 0.f);
    ob[6 * HW] = fmaxf(fmaf(c.z, ssc[6], ssh[6]), 0.f);
    ob[7 * HW] = fmaxf(fmaf(c.w, ssc[7], ssh[7]), 0.f);
}

extern "C" void kernel_launch(void* const* d_in, const int* in_sizes, int n_in,
                              void* d_out, int out_size) {
    const float* x     = (const float*)d_in[0];
    const float* lin_w = (const float*)d_in[1];
    const float* lin_b = (const float*)d_in[2];
    const float* gamma = (const float*)d_in[3];
    const float* beta  = (const float*)d_in[4];
    float* out = (float*)d_out;

    dim3 grid(TILES_X, TILES_Y, BATCH);
    conv_kernel<<<grid, 128>>>(x, lin_w, lin_b);
    stats_kernel<<<1, 1024>>>(gamma, beta);
    int npix = BATCH * HH * WW;   // 4194304
    norm_kernel<<<npix / 256, 256>>>(out);
}